// round 6
// baseline (speedup 1.0000x reference)
#include <cuda_runtime.h>

// ---------------------------------------------------------------------------
// Problem constants
// ---------------------------------------------------------------------------
#define BATCH   8
#define CH      64        // C_IN == C_OUT == GROUPS == 64  (depthwise)
#define HH      256
#define WW      256
#define KK      3
#define REP_DIM 512
#define ROWS_PER_WARP 8   // one warp computes 8 consecutive output rows

// ---------------------------------------------------------------------------
// Row loader: one warp loads a full 256-float row as 2 coalesced float4s per
// lane and resolves ALL horizontal halos (interior + mid-row seam +
// reflection edges) with warp shuffles. Zero scalar LDGs.
//
//   group0: lane j owns elements [4j .. 4j+3]        (w = 0..127)
//   group1: lane j owns elements [128+4j .. 131+4j]  (w = 128..255)
//
// r[0..5]  = [left halo, v0.x, v0.y, v0.z, v0.w, right halo]  (group0)
// r[6..11] = [left halo, v1.x, v1.y, v1.z, v1.w, right halo]  (group1)
// ---------------------------------------------------------------------------
__device__ __forceinline__ void load_row(const float* __restrict__ row,
                                         int lane, float* r) {
    const unsigned FULL = 0xffffffffu;
    float4 v0 = *reinterpret_cast<const float4*>(row + lane * 4);
    float4 v1 = *reinterpret_cast<const float4*>(row + 128 + lane * 4);

    float up0  = __shfl_up_sync  (FULL, v0.w, 1);   // elem 4j-1   (j>0)
    float dn0  = __shfl_down_sync(FULL, v0.x, 1);   // elem 4j+4   (j<31)
    float b10  = __shfl_sync     (FULL, v1.x, 0);   // elem 128    (seam)
    float up1  = __shfl_up_sync  (FULL, v1.w, 1);   // elem 127+4j (j>0)
    float b031 = __shfl_sync     (FULL, v0.w, 31);  // elem 127    (seam)
    float dn1  = __shfl_down_sync(FULL, v1.x, 1);   // elem 132+4j (j<31)

    // Reflection pad: w=-1 -> w=1 (lane0 own v0.y); w=256 -> w=254 (lane31 own v1.z)
    r[0]  = (lane == 0)  ? v0.y : up0;
    r[1]  = v0.x; r[2] = v0.y; r[3] = v0.z; r[4] = v0.w;
    r[5]  = (lane == 31) ? b10  : dn0;
    r[6]  = (lane == 0)  ? b031 : up1;
    r[7]  = v1.x; r[8] = v1.y; r[9] = v1.z; r[10] = v1.w;
    r[11] = (lane == 31) ? v1.z : dn1;
}

// ---------------------------------------------------------------------------
// Fused kernel:
//   Phase A (per block): compute this channel's 9 dynamic taps
//     tap[t] = leaky_relu( dot(rep[b], w_key[c*9+t]), 0.1 )
//     8 warps cover 9 taps (warp 0 takes taps 0 and 8). w_key rows are
//     L2-hot across the 64 blocks that share a channel.
//   Phase B: per-sample depthwise 3x3 conv, reflection pad=1.
//     grid: (HH/(8*ROWS_PER_WARP), CH, BATCH), block: (32, 8).
//     One warp computes ROWS_PER_WARP consecutive output rows with a rolling
//     3-row register buffer: (ROWS_PER_WARP+2) row loads per ROWS_PER_WARP rows.
// ---------------------------------------------------------------------------
__global__ __launch_bounds__(256)
void sconv_fused_kernel(const float* __restrict__ x,
                        const float* __restrict__ rep,
                        const float* __restrict__ wkey,
                        float* __restrict__ out) {
    const int lane = threadIdx.x;   // 0..31
    const int wid  = threadIdx.y;   // 0..7
    const int c    = blockIdx.y;
    const int b    = blockIdx.z;

    __shared__ float s_k[KK * KK];

    // ---------------- Phase A: dynamic taps ----------------
    {
        const unsigned FULL = 0xffffffffu;
        const float4* r4 = reinterpret_cast<const float4*>(rep + b * REP_DIM);
        #pragma unroll 2
        for (int tap = wid; tap < KK * KK; tap += 8) {
            const float4* w4 = reinterpret_cast<const float4*>(
                wkey + (size_t)(c * KK * KK + tap) * REP_DIM);
            float s = 0.0f;
            #pragma unroll
            for (int i = lane; i < REP_DIM / 4; i += 32) {
                float4 a = r4[i];
                float4 w = w4[i];
                s += a.x * w.x + a.y * w.y + a.z * w.z + a.w * w.w;
            }
            #pragma unroll
            for (int o = 16; o > 0; o >>= 1)
                s += __shfl_xor_sync(FULL, s, o);
            if (lane == 0)
                s_k[tap] = (s > 0.0f) ? s : 0.1f * s;
        }
    }
    __syncthreads();

    const float k00 = s_k[0], k01 = s_k[1], k02 = s_k[2];
    const float k10 = s_k[3], k11 = s_k[4], k12 = s_k[5];
    const float k20 = s_k[6], k21 = s_k[7], k22 = s_k[8];

    // ---------------- Phase B: depthwise conv ----------------
    const int h0 = (blockIdx.x * 8 + wid) * ROWS_PER_WARP;

    const float* img = x + ((size_t)(b * CH + c)) * HH * WW;
    float* dst_base  = out + ((size_t)(b * CH + c)) * HH * WW;

    // Rolling 3-row register buffer. Fully unrolled loop keeps it in regs.
    float R[3][12];

    // Prime: row (h0-1) reflected, and row h0.
    {
        const int hm = (h0 == 0) ? 1 : h0 - 1;   // reflect top edge
        load_row(img + (size_t)hm * WW, lane, R[0]);
        load_row(img + (size_t)h0 * WW, lane, R[1]);
    }

    #pragma unroll
    for (int i = 0; i < ROWS_PER_WARP; i++) {
        const int h  = h0 + i;
        const int hn = (h == HH - 1) ? HH - 2 : h + 1;  // reflect bottom edge
        load_row(img + (size_t)hn * WW, lane, R[(i + 2) % 3]);

        const float* rA = R[i % 3];        // row h-1
        const float* rB = R[(i + 1) % 3];  // row h
        const float* rC = R[(i + 2) % 3];  // row h+1

        float4 oA, oB;
        float* a  = &oA.x;
        float* bb = &oB.x;
        #pragma unroll
        for (int j = 0; j < 4; j++) {
            a[j]  = k00 * rA[j]     + k01 * rA[j + 1] + k02 * rA[j + 2]
                  + k10 * rB[j]     + k11 * rB[j + 1] + k12 * rB[j + 2]
                  + k20 * rC[j]     + k21 * rC[j + 1] + k22 * rC[j + 2];
            bb[j] = k00 * rA[j + 6] + k01 * rA[j + 7] + k02 * rA[j + 8]
                  + k10 * rB[j + 6] + k11 * rB[j + 7] + k12 * rB[j + 8]
                  + k20 * rC[j + 6] + k21 * rC[j + 7] + k22 * rC[j + 8];
        }

        float* dst = dst_base + (size_t)h * WW;
        *reinterpret_cast<float4*>(dst + lane * 4)       = oA;
        *reinterpret_cast<float4*>(dst + 128 + lane * 4) = oB;
    }
}

// ---------------------------------------------------------------------------
// Launch
// Inputs (metadata order): d_in[0]=x [8,64,256,256] f32,
//                          d_in[1]=representation [8,512] f32,
//                          d_in[2]=w_key [576,512] f32
// Output: f32 [8,64,256,256]
// ---------------------------------------------------------------------------
extern "C" void kernel_launch(void* const* d_in, const int* in_sizes, int n_in,
                              void* d_out, int out_size) {
    const float* x    = (const float*)d_in[0];
    const float* rep  = (const float*)d_in[1];
    const float* wkey = (const float*)d_in[2];
    float* out        = (float*)d_out;

    dim3 grid(HH / (8 * ROWS_PER_WARP), CH, BATCH);  // (4, 64, 8) = 2048 blocks
    dim3 block(32, 8);
    sconv_fused_kernel<<<grid, block>>>(x, rep, wkey, out);
}

// round 7
// speedup vs baseline: 1.1302x; 1.1302x over previous
#include <cuda_runtime.h>

// ---------------------------------------------------------------------------
// Problem constants
// ---------------------------------------------------------------------------
#define BATCH   8
#define CH      64        // C_IN == C_OUT == GROUPS == 64  (depthwise)
#define HH      256
#define WW      256
#define KK      3
#define REP_DIM 512
#define NFEAT   (CH * KK * KK)   // 576
#define ROWS_PER_WARP 4

// Scratch for the per-sample dynamic 3x3 kernels (post leaky-relu).
__device__ float g_kern[BATCH * NFEAT];

// ---------------------------------------------------------------------------
// Stage 1: kern[b][f] = leaky_relu( sum_r rep[b][r] * w_key[f][r], 0.1 )
// One warp per (b, f). float4 vectorized dot over 512 elements.
// ---------------------------------------------------------------------------
__global__ void keygen_kernel(const float* __restrict__ rep,
                              const float* __restrict__ wkey) {
    int gid  = blockIdx.x * blockDim.x + threadIdx.x;
    int warp = gid >> 5;
    int lane = gid & 31;
    if (warp >= BATCH * NFEAT) return;

    int b = warp / NFEAT;
    int f = warp % NFEAT;

    const float4* r4 = reinterpret_cast<const float4*>(rep + b * REP_DIM);
    const float4* w4 = reinterpret_cast<const float4*>(wkey + f * REP_DIM);

    float s = 0.0f;
    #pragma unroll
    for (int i = lane; i < REP_DIM / 4; i += 32) {
        float4 a = r4[i];
        float4 w = w4[i];
        s += a.x * w.x + a.y * w.y + a.z * w.z + a.w * w.w;
    }
    #pragma unroll
    for (int o = 16; o > 0; o >>= 1)
        s += __shfl_xor_sync(0xffffffffu, s, o);

    if (lane == 0) {
        g_kern[warp] = (s > 0.0f) ? s : 0.1f * s;
    }
}

// ---------------------------------------------------------------------------
// Row loader: one warp loads a full 256-float row as 2 coalesced float4s per
// lane and resolves ALL horizontal halos (interior + mid-row seam +
// reflection edges) with warp shuffles. Zero scalar LDGs.
//
//   group0: lane j owns elements [4j .. 4j+3]        (w = 0..127)
//   group1: lane j owns elements [128+4j .. 131+4j]  (w = 128..255)
//
// r[0..5]  = [left halo, v0.x, v0.y, v0.z, v0.w, right halo]  (group0)
// r[6..11] = [left halo, v1.x, v1.y, v1.z, v1.w, right halo]  (group1)
// ---------------------------------------------------------------------------
__device__ __forceinline__ void load_row(const float* __restrict__ row,
                                         int lane, float* r) {
    const unsigned FULL = 0xffffffffu;
    float4 v0 = *reinterpret_cast<const float4*>(row + lane * 4);
    float4 v1 = *reinterpret_cast<const float4*>(row + 128 + lane * 4);

    float up0  = __shfl_up_sync  (FULL, v0.w, 1);   // elem 4j-1   (j>0)
    float dn0  = __shfl_down_sync(FULL, v0.x, 1);   // elem 4j+4   (j<31)
    float b10  = __shfl_sync     (FULL, v1.x, 0);   // elem 128    (seam)
    float up1  = __shfl_up_sync  (FULL, v1.w, 1);   // elem 127+4j (j>0)
    float b031 = __shfl_sync     (FULL, v0.w, 31);  // elem 127    (seam)
    float dn1  = __shfl_down_sync(FULL, v1.x, 1);   // elem 132+4j (j<31)

    // Reflection pad: w=-1 -> w=1 (lane0 own v0.y); w=256 -> w=254 (lane31 own v1.z)
    r[0]  = (lane == 0)  ? v0.y : up0;
    r[1]  = v0.x; r[2] = v0.y; r[3] = v0.z; r[4] = v0.w;
    r[5]  = (lane == 31) ? b10  : dn0;
    r[6]  = (lane == 0)  ? b031 : up1;
    r[7]  = v1.x; r[8] = v1.y; r[9] = v1.z; r[10] = v1.w;
    r[11] = (lane == 31) ? v1.z : dn1;
}

// ---------------------------------------------------------------------------
// Stage 2: per-sample depthwise 3x3 conv with reflection padding (pad=1).
// grid: (HH/(8*ROWS_PER_WARP), CH, BATCH), block: (32, 8).
// One warp computes ROWS_PER_WARP=4 consecutive output rows with a rolling
// 3-row register buffer: 6 row loads per 4 output rows.
// Output uses streaming stores (__stcs) — the result is never re-read, so
// evict-first keeps L2 capacity for the input x working set.
// ---------------------------------------------------------------------------
__global__ __launch_bounds__(256)
void dwconv_kernel(const float* __restrict__ x, float* __restrict__ out) {
    const int lane = threadIdx.x;                                  // 0..31
    const int h0   = (blockIdx.x * 8 + threadIdx.y) * ROWS_PER_WARP;
    const int c    = blockIdx.y;
    const int b    = blockIdx.z;

    const float* kp = &g_kern[(b * CH + c) * (KK * KK)];
    const float k00 = __ldg(kp + 0), k01 = __ldg(kp + 1), k02 = __ldg(kp + 2);
    const float k10 = __ldg(kp + 3), k11 = __ldg(kp + 4), k12 = __ldg(kp + 5);
    const float k20 = __ldg(kp + 6), k21 = __ldg(kp + 7), k22 = __ldg(kp + 8);

    const float* img = x + ((size_t)(b * CH + c)) * HH * WW;
    float* dst_base  = out + ((size_t)(b * CH + c)) * HH * WW;

    // Rolling 3-row register buffer. Fully unrolled loop keeps it in regs.
    float R[3][12];

    // Prime: row (h0-1) reflected, and row h0.
    {
        const int hm = (h0 == 0) ? 1 : h0 - 1;   // reflect top edge
        load_row(img + (size_t)hm * WW, lane, R[0]);
        load_row(img + (size_t)h0 * WW, lane, R[1]);
    }

    #pragma unroll
    for (int i = 0; i < ROWS_PER_WARP; i++) {
        const int h  = h0 + i;
        const int hn = (h == HH - 1) ? HH - 2 : h + 1;  // reflect bottom edge
        load_row(img + (size_t)hn * WW, lane, R[(i + 2) % 3]);

        const float* rA = R[i % 3];        // row h-1
        const float* rB = R[(i + 1) % 3];  // row h
        const float* rC = R[(i + 2) % 3];  // row h+1

        float4 oA, oB;
        float* a  = &oA.x;
        float* bb = &oB.x;
        #pragma unroll
        for (int j = 0; j < 4; j++) {
            a[j]  = k00 * rA[j]     + k01 * rA[j + 1] + k02 * rA[j + 2]
                  + k10 * rB[j]     + k11 * rB[j + 1] + k12 * rB[j + 2]
                  + k20 * rC[j]     + k21 * rC[j + 1] + k22 * rC[j + 2];
            bb[j] = k00 * rA[j + 6] + k01 * rA[j + 7] + k02 * rA[j + 8]
                  + k10 * rB[j + 6] + k11 * rB[j + 7] + k12 * rB[j + 8]
                  + k20 * rC[j + 6] + k21 * rC[j + 7] + k22 * rC[j + 8];
        }

        float* dst = dst_base + (size_t)h * WW;
        __stcs(reinterpret_cast<float4*>(dst + lane * 4), oA);
        __stcs(reinterpret_cast<float4*>(dst + 128 + lane * 4), oB);
    }
}

// ---------------------------------------------------------------------------
// Launch
// Inputs (metadata order): d_in[0]=x [8,64,256,256] f32,
//                          d_in[1]=representation [8,512] f32,
//                          d_in[2]=w_key [576,512] f32
// Output: f32 [8,64,256,256]
// ---------------------------------------------------------------------------
extern "C" void kernel_launch(void* const* d_in, const int* in_sizes, int n_in,
                              void* d_out, int out_size) {
    const float* x    = (const float*)d_in[0];
    const float* rep  = (const float*)d_in[1];
    const float* wkey = (const float*)d_in[2];
    float* out        = (float*)d_out;

    // Stage 1: 8*576 warps -> 576 blocks of 256 threads
    {
        int warps   = BATCH * NFEAT;
        int threads = warps * 32;
        int blocks  = (threads + 255) / 256;
        keygen_kernel<<<blocks, 256>>>(rep, wkey);
    }

    // Stage 2: depthwise conv, one warp per 4 output rows
    {
        dim3 grid(HH / (8 * ROWS_PER_WARP), CH, BATCH);  // (8, 64, 8) = 4096
        dim3 block(32, 8);
        dwconv_kernel<<<grid, block>>>(x, out);
    }
}